// round 2
// baseline (speedup 1.0000x reference)
#include <cuda_runtime.h>
#include <cuda_bf16.h>

// Problem constants (z: [32,64,64,64] f32, codebook: [1024,64] f32)
#define BB      32
#define CC      64
#define HWN     4096            // H*W
#define NQ      (BB * HWN)      // 131072 query vectors
#define KCODES  1024
#define TILE    128             // codes per smem tile (128*64*4 = 32KB)
#define THREADS 256
#define NBLOCKS (NQ / THREADS)  // 512
#define ZELEMS  (BB * CC * HWN) // 8388608
#define EPS     4e-3f           // refinement window (>> fp32 score error ~1e-4)

__device__ float g_cnorm[KCODES];
__device__ float g_partials[NBLOCKS];

// packed f32x2 helpers (sm_103a)
#define FMA2(acc, a, b) \
    asm("fma.rn.f32x2 %0, %1, %2, %0;" : "+l"(acc) : "l"(a), "l"(b))
#define ADD2(d, a, b) \
    asm("add.rn.f32x2 %0, %1, %2;" : "=l"(d) : "l"(a), "l"(b))
#define PACK2(d, lo, hi) \
    asm("mov.b64 %0, {%1, %2};" : "=l"(d) : "f"(lo), "f"(hi))
#define UNPACK2(lo, hi, s) \
    asm("mov.b64 {%0, %1}, %2;" : "=f"(lo), "=f"(hi) : "l"(s))

// ---------------------------------------------------------------------------
// Kernel 0: codebook row norms ||c_k||^2
// ---------------------------------------------------------------------------
__global__ void cnorm_kernel(const float* __restrict__ cb) {
    int k = blockIdx.x * blockDim.x + threadIdx.x;
    if (k < KCODES) {
        const float4* r = reinterpret_cast<const float4*>(cb + (size_t)k * CC);
        float s = 0.f;
#pragma unroll
        for (int i = 0; i < CC / 4; i++) {
            float4 v = __ldg(r + i);
            s += v.x * v.x;
            s += v.y * v.y;
            s += v.z * v.z;
            s += v.w * v.w;
        }
        g_cnorm[k] = s;
    }
}

// exact (fp64) squared distance between query regs (packed pairs) and code row
__device__ __forceinline__ double dist2_f64(const unsigned long long* zq,
                                            const float* __restrict__ cb,
                                            int idx) {
    const float2* cp = reinterpret_cast<const float2*>(cb + (size_t)idx * CC);
    double d = 0.0;
#pragma unroll
    for (int i = 0; i < CC / 2; i++) {
        float zlo, zhi;
        UNPACK2(zlo, zhi, zq[i]);
        float2 c = __ldg(cp + i);
        double d0 = (double)zlo - (double)c.x;
        double d1 = (double)zhi - (double)c.y;
        d = fma(d0, d0, d);
        d = fma(d1, d1, d);
    }
    return d;
}

// ---------------------------------------------------------------------------
// Kernel 1: nearest-code search + fp64 near-tie refinement + z_q scatter
// ---------------------------------------------------------------------------
__global__ __launch_bounds__(THREADS, 2)
void vq_kernel(const float* __restrict__ z,
               const float* __restrict__ cb,
               float* __restrict__ out) {
    __shared__ ulonglong2 sc[TILE * 16];  // 128 codes * 64 floats = 32KB
    __shared__ float scn[TILE];
    __shared__ float werr[THREADS / 32];

    const int q = blockIdx.x * THREADS + threadIdx.x;
    const int b = q >> 12;        // q / 4096
    const int n = q & (HWN - 1);  // q % 4096

    const float* zp = z + (size_t)b * CC * HWN + n;

    // Load query into 32 packed f32x2 registers.
    unsigned long long zq[CC / 2];
#pragma unroll
    for (int i = 0; i < CC / 2; i++) {
        float x = zp[(size_t)(2 * i) * HWN];
        float y = zp[(size_t)(2 * i + 1) * HWN];
        PACK2(zq[i], x, y);
    }

    // Top-4 candidates (scores ascending). score = ||c||^2 - 2 z.c
    float s0 = 3.4e38f, s1 = 3.4e38f, s2 = 3.4e38f, s3 = 3.4e38f;
    int   i0 = 0,       i1 = 0,       i2 = 0,       i3 = 0;

    for (int t = 0; t < KCODES; t += TILE) {
        __syncthreads();
        // Stage codebook tile (coalesced float4 loads).
        {
            const float4* g4 = reinterpret_cast<const float4*>(cb + (size_t)t * CC);
            float4* s4 = reinterpret_cast<float4*>(sc);
            for (int i = threadIdx.x; i < TILE * 16; i += THREADS)
                s4[i] = __ldg(g4 + i);
            if (threadIdx.x < TILE)
                scn[threadIdx.x] = g_cnorm[t + threadIdx.x];
        }
        __syncthreads();

#pragma unroll 2
        for (int k = 0; k < TILE; k++) {
            const ulonglong2* cp = sc + k * 16;
            unsigned long long a0 = 0ull, a1 = 0ull, a2 = 0ull, a3 = 0ull;
#pragma unroll
            for (int i = 0; i < 16; i += 2) {
                ulonglong2 v0 = cp[i];
                ulonglong2 v1 = cp[i + 1];
                FMA2(a0, zq[2 * i + 0], v0.x);
                FMA2(a1, zq[2 * i + 1], v0.y);
                FMA2(a2, zq[2 * i + 2], v1.x);
                FMA2(a3, zq[2 * i + 3], v1.y);
            }
            unsigned long long p01, p23, pall;
            ADD2(p01, a0, a1);
            ADD2(p23, a2, a3);
            ADD2(pall, p01, p23);
            float lo, hi;
            UNPACK2(lo, hi, pall);
            float dot = lo + hi;
            float score = fmaf(-2.f, dot, scn[k]);
            // top-4 insertion (strict < keeps earliest index on equal score)
            if (score < s3) {
                int idx = t + k;
                if (score < s0) {
                    s3 = s2; i3 = i2; s2 = s1; i2 = i1; s1 = s0; i1 = i0;
                    s0 = score; i0 = idx;
                } else if (score < s1) {
                    s3 = s2; i3 = i2; s2 = s1; i2 = i1;
                    s1 = score; i1 = idx;
                } else if (score < s2) {
                    s3 = s2; i3 = i2;
                    s2 = score; i2 = idx;
                } else {
                    s3 = score; i3 = idx;
                }
            }
        }
    }

    // fp64 refinement among near-tied candidates (rare; exact-math argmin).
    int bidx = i0;
    if (s1 < s0 + EPS) {
        double bd = dist2_f64(zq, cb, i0);
        float ss[3] = {s1, s2, s3};
        int   ii[3] = {i1, i2, i3};
#pragma unroll
        for (int c = 0; c < 3; c++) {
            if (ss[c] < s0 + EPS) {
                double d = dist2_f64(zq, cb, ii[c]);
                if (d < bd || (d == bd && ii[c] < bidx)) { bd = d; bidx = ii[c]; }
            }
        }
    }

    // Epilogue: gather winning code, write z_q, accumulate squared error.
    float err = 0.f;
    {
        const float4* cv4 = reinterpret_cast<const float4*>(cb + (size_t)bidx * CC);
        float* op = out + (size_t)b * CC * HWN + n;
#pragma unroll
        for (int i = 0; i < CC / 4; i++) {
            float4 v = __ldg(cv4 + i);
            float z0, z1, z2, z3, zw0, zw1;
            UNPACK2(z0, z1, zq[2 * i]);
            UNPACK2(z2, z3, zq[2 * i + 1]);
            (void)zw0; (void)zw1;
            op[(size_t)(4 * i + 0) * HWN] = v.x;
            op[(size_t)(4 * i + 1) * HWN] = v.y;
            op[(size_t)(4 * i + 2) * HWN] = v.z;
            op[(size_t)(4 * i + 3) * HWN] = v.w;
            float d0 = v.x - z0, d1 = v.y - z1, d2 = v.z - z2, d3 = v.w - z3;
            err = fmaf(d0, d0, err);
            err = fmaf(d1, d1, err);
            err = fmaf(d2, d2, err);
            err = fmaf(d3, d3, err);
        }
    }

    // Deterministic block reduction of err.
#pragma unroll
    for (int o = 16; o > 0; o >>= 1)
        err += __shfl_down_sync(0xFFFFFFFFu, err, o);
    if ((threadIdx.x & 31) == 0)
        werr[threadIdx.x >> 5] = err;
    __syncthreads();
    if (threadIdx.x == 0) {
        float s = 0.f;
#pragma unroll
        for (int i = 0; i < THREADS / 32; i++) s += werr[i];
        g_partials[blockIdx.x] = s;
    }
}

// ---------------------------------------------------------------------------
// Kernel 2: deterministic final loss reduction
// loss = (1 + BETA) * mean((z_q - z)^2), BETA = 0.25
// ---------------------------------------------------------------------------
__global__ void loss_kernel(float* __restrict__ loss_out) {
    __shared__ double s[512];
    double v = (threadIdx.x < NBLOCKS) ? (double)g_partials[threadIdx.x] : 0.0;
    s[threadIdx.x] = v;
    __syncthreads();
#pragma unroll
    for (int st = 256; st > 0; st >>= 1) {
        if (threadIdx.x < st) s[threadIdx.x] += s[threadIdx.x + st];
        __syncthreads();
    }
    if (threadIdx.x == 0)
        loss_out[0] = (float)(1.25 * s[0] / (double)ZELEMS);
}

// ---------------------------------------------------------------------------
extern "C" void kernel_launch(void* const* d_in, const int* in_sizes, int n_in,
                              void* d_out, int out_size) {
    const float* z  = (const float*)d_in[0];
    const float* cb = (const float*)d_in[1];
    float* out = (float*)d_out;

    cnorm_kernel<<<(KCODES + 255) / 256, 256>>>(cb);
    vq_kernel<<<NBLOCKS, THREADS>>>(z, cb, out);
    if (out_size > ZELEMS)
        loss_kernel<<<1, 512>>>(out + ZELEMS);
}

// round 4
// speedup vs baseline: 1.4445x; 1.4445x over previous
#include <cuda_runtime.h>
#include <cuda_bf16.h>
#include <cstdint>

// Problem constants (z: [32,64,64,64] f32, codebook: [1024,64] f32)
#define BB      32
#define CC      64
#define HWN     4096
#define NQ      (BB * HWN)        // 131072 queries
#define KCODES  1024
#define MTILE   128               // queries per CTA
#define NCHUNK  128               // codes staged per smem chunk
#define THREADS 128
#define NBLOCKS (NQ / MTILE)      // 1024
#define ZELEMS  (BB * CC * HWN)
#define EPS     4e-3f
#define PADW    136               // bf16 row stride: 272B = 17*16B -> LDSM conflict-free

// dynamic smem layout (bytes)
#define OFF_A    0                            // 128 x 136 bf16 = 34816 (z: [hi64|lo64|pad])
#define OFF_B    34816                        // 128 x 136 bf16 = 34816 (codes: [hi64|lo64|pad])
#define OFF_SCN  69632                        // 128 floats
#define OFF_WERR 70144                        // 4 floats
#define OFF_CAND 70160                        // 128 * 17 float2 = 17408
#define SMEM_TOTAL (OFF_CAND + 17408)         // 87568

__device__ float g_cnorm[KCODES];
__device__ float g_partials[NBLOCKS];
// prepped codebook: bf16 hi/lo of (-2c), rows padded to PADW
__device__ __align__(16) __nv_bfloat16 g_cbimg[KCODES * PADW];

// ---------------------------------------------------------------------------
__device__ __forceinline__ uint32_t smem_to_u32(const void* p) {
    uint32_t a;
    asm("{ .reg .u64 t; cvta.to.shared.u64 t, %1; cvt.u32.u64 %0, t; }"
        : "=r"(a) : "l"(p));
    return a;
}

#define LDSM_X4(r, addr) \
    asm volatile("ldmatrix.sync.aligned.m8n8.x4.shared.b16 {%0,%1,%2,%3}, [%4];" \
        : "=r"((r)[0]), "=r"((r)[1]), "=r"((r)[2]), "=r"((r)[3]) : "r"(addr))

#define MMA16816(d, a, b) \
    asm volatile("mma.sync.aligned.m16n8k16.row.col.f32.bf16.bf16.f32 " \
        "{%0,%1,%2,%3}, {%4,%5,%6,%7}, {%8,%9}, {%0,%1,%2,%3};" \
        : "+f"((d)[0]), "+f"((d)[1]), "+f"((d)[2]), "+f"((d)[3]) \
        : "r"((a)[0]), "r"((a)[1]), "r"((a)[2]), "r"((a)[3]), \
          "r"((b)[0]), "r"((b)[1]))

__device__ __forceinline__ void top4_insert(float s, int idx, float* ts, int* ti) {
    if (s < ts[3]) {
        if (s < ts[0]) {
            ts[3]=ts[2]; ti[3]=ti[2]; ts[2]=ts[1]; ti[2]=ti[1];
            ts[1]=ts[0]; ti[1]=ti[0]; ts[0]=s; ti[0]=idx;
        } else if (s < ts[1]) {
            ts[3]=ts[2]; ti[3]=ti[2]; ts[2]=ts[1]; ti[2]=ti[1]; ts[1]=s; ti[1]=idx;
        } else if (s < ts[2]) {
            ts[3]=ts[2]; ti[3]=ti[2]; ts[2]=s; ti[2]=idx;
        } else {
            ts[3]=s; ti[3]=idx;
        }
    }
}

// ---------------------------------------------------------------------------
// Kernel 0: prep — cn = ||c||^2, bf16 hi/lo split of (-2c), padded rows
// ---------------------------------------------------------------------------
__global__ void prep_kernel(const float* __restrict__ cb) {
    int k = blockIdx.x * blockDim.x + threadIdx.x;
    if (k >= KCODES) return;
    const float* r = cb + (size_t)k * CC;
    __nv_bfloat16* row = g_cbimg + (size_t)k * PADW;
    float cn = 0.f;
#pragma unroll
    for (int c = 0; c < CC; c++) {
        float v = r[c];
        cn = fmaf(v, v, cn);
        float s = -2.f * v;
        __nv_bfloat16 h = __float2bfloat16_rn(s);
        __nv_bfloat16 lo = __float2bfloat16_rn(s - __bfloat162float(h));
        row[c] = h;
        row[CC + c] = lo;
    }
    row[2 * CC + 0] = __nv_bfloat16(0.f);  // pad (unused by LDSM reads)
    g_cnorm[k] = cn;
}

// exact fp64 squared distance (refinement path)
__device__ double dist2_f64(const float* __restrict__ zp,
                            const float* __restrict__ cb, int idx) {
    const float* cp = cb + (size_t)idx * CC;
    double d = 0.0;
#pragma unroll
    for (int c = 0; c < CC; c++) {
        double df = (double)zp[(size_t)c * HWN] - (double)cp[c];
        d = fma(df, df, d);
    }
    return d;
}

// ---------------------------------------------------------------------------
// Kernel 1: HMMA VQ — D = cn - 2 z.c via mma.sync bf16x3, exact argmin
// ---------------------------------------------------------------------------
extern __shared__ unsigned char dynsmem[];

__global__ __launch_bounds__(THREADS)
void vq_kernel(const float* __restrict__ z,
               const float* __restrict__ cb,
               float* __restrict__ out) {
    const int tid = threadIdx.x;
    const int w = tid >> 5;
    const int l = tid & 31;
    const uint32_t sb = smem_to_u32(dynsmem);

    __nv_bfloat16* A = reinterpret_cast<__nv_bfloat16*>(dynsmem + OFF_A);
    float* scn  = reinterpret_cast<float*>(dynsmem + OFF_SCN);
    float* werr = reinterpret_cast<float*>(dynsmem + OFF_WERR);
    float2* cand = reinterpret_cast<float2*>(dynsmem + OFF_CAND);

    const int q = blockIdx.x * MTILE + tid;
    const int b = q >> 12;
    const float* zp = z + (size_t)b * CC * HWN + (q & (HWN - 1));

    // --- A tile: z query -> bf16 hi/lo, row-major padded ---
#pragma unroll
    for (int c = 0; c < CC; c++) {
        float v = zp[(size_t)c * HWN];
        __nv_bfloat16 h = __float2bfloat16_rn(v);
        A[tid * PADW + c] = h;
        A[tid * PADW + CC + c] = __float2bfloat16_rn(v - __bfloat162float(h));
    }

    // per-thread top-4 over 4 query-slots (16 disjoint code-subsets)
    float ts[16];
    int   ti[16];
#pragma unroll
    for (int i = 0; i < 16; i++) { ts[i] = 3.4e38f; ti[i] = 0x7fffffff; }

    // LDSM per-thread address components
    const int rowA = w * 32 + (l & 15);          // + mt*16
    const int colA = ((l >> 4) & 1) * 8;
    const int rowB = ((l >> 4) & 1) * 8 + (l & 7);  // within 16-row group
    const int colB = ((l >> 3) & 1) * 8;

    // stacked-K split schedule: zh*bh (4), zl*bh (4), zh*bl (4)
    const int KA[12] = {0,16,32,48, 64,80,96,112, 0,16,32,48};
    const int KB[12] = {0,16,32,48, 0,16,32,48, 64,80,96,112};

    for (int ch = 0; ch < KCODES / NCHUNK; ch++) {
        __syncthreads();
        // stage code chunk (prepped, padded rows -> linear int4 copy)
        {
            const int4* src = reinterpret_cast<const int4*>(g_cbimg + (size_t)ch * NCHUNK * PADW);
            int4* dst = reinterpret_cast<int4*>(dynsmem + OFF_B);
#pragma unroll 4
            for (int i = tid; i < NCHUNK * PADW * 2 / 16; i += THREADS) dst[i] = src[i];
            scn[tid] = g_cnorm[ch * NCHUNK + tid];
        }
        __syncthreads();

#pragma unroll 1
        for (int nsub = 0; nsub < 4; nsub++) {
            // accum init: d[(mt*4+nt)*4+e] = cn[n(e)]
            float d[32];
#pragma unroll
            for (int nt = 0; nt < 4; nt++) {
                float cn0 = scn[nsub * 32 + nt * 8 + 2 * (l & 3)];
                float cn1 = scn[nsub * 32 + nt * 8 + 2 * (l & 3) + 1];
#pragma unroll
                for (int mt = 0; mt < 2; mt++) {
                    d[(mt * 4 + nt) * 4 + 0] = cn0;
                    d[(mt * 4 + nt) * 4 + 1] = cn1;
                    d[(mt * 4 + nt) * 4 + 2] = cn0;
                    d[(mt * 4 + nt) * 4 + 3] = cn1;
                }
            }

#pragma unroll
            for (int step = 0; step < 12; step++) {
                const int ka = KA[step], kb = KB[step];
                uint32_t a0[4], a1[4], bf[8];
                LDSM_X4(a0, sb + OFF_A + (uint32_t)((rowA)      * PADW + colA + ka) * 2);
                LDSM_X4(a1, sb + OFF_A + (uint32_t)((rowA + 16) * PADW + colA + ka) * 2);
                LDSM_X4(bf,     sb + OFF_B + (uint32_t)((nsub * 32 +      rowB) * PADW + colB + kb) * 2);
                LDSM_X4(bf + 4, sb + OFF_B + (uint32_t)((nsub * 32 + 16 + rowB) * PADW + colB + kb) * 2);
#pragma unroll
                for (int nt = 0; nt < 4; nt++) {
                    MMA16816(d + (0 * 4 + nt) * 4, a0, bf + nt * 2);
                    MMA16816(d + (1 * 4 + nt) * 4, a1, bf + nt * 2);
                }
            }

            // top-4 update: slot = mt*2 + (e>>1)
#pragma unroll
            for (int mt = 0; mt < 2; mt++)
#pragma unroll
                for (int nt = 0; nt < 4; nt++)
#pragma unroll
                    for (int e = 0; e < 4; e++) {
                        float s = d[(mt * 4 + nt) * 4 + e];
                        int idx = ch * NCHUNK + nsub * 32 + nt * 8 + 2 * (l & 3) + (e & 1);
                        int slot = mt * 2 + (e >> 1);
                        top4_insert(s, idx, ts + slot * 4, ti + slot * 4);
                    }
        }
    }

    // --- merge candidates via smem (stride 17 float2 to dodge bank conflicts) ---
    __syncthreads();
#pragma unroll
    for (int s = 0; s < 4; s++) {
        int mt = s >> 1, half = s & 1;
        int ql = w * 32 + mt * 16 + half * 8 + (l >> 2);
#pragma unroll
        for (int e = 0; e < 4; e++)
            cand[ql * 17 + (l & 3) * 4 + e] =
                make_float2(ts[s * 4 + e], __int_as_float(ti[s * 4 + e]));
    }
    __syncthreads();

    // --- per-query (thread = query): window + fp64 refinement ---
    float cs[16]; int ci[16];
#pragma unroll
    for (int j = 0; j < 16; j++) {
        float2 v = cand[tid * 17 + j];
        cs[j] = v.x; ci[j] = __float_as_int(v.y);
    }
    float smin = cs[0];
#pragma unroll
    for (int j = 1; j < 16; j++) smin = fminf(smin, cs[j]);

    int nwin = 0, lone = 0;
#pragma unroll
    for (int j = 0; j < 16; j++)
        if (cs[j] < smin + EPS) { nwin++; lone = j; }

    int bidx;
    if (nwin == 1) {
        bidx = ci[lone];
    } else {
        double bd = 1e300;
        int bi = 0x7fffffff;
#pragma unroll
        for (int j = 0; j < 16; j++) {
            if (cs[j] < smin + EPS) {
                double dd = dist2_f64(zp, cb, ci[j]);
                if (dd < bd || (dd == bd && ci[j] < bi)) { bd = dd; bi = ci[j]; }
            }
        }
        bidx = bi;
    }

    // --- write z_q + squared-error partial (coalesced: threads = consecutive n) ---
    float err = 0.f;
    {
        const float* cv = cb + (size_t)bidx * CC;
        float* op = out + (size_t)b * CC * HWN + (q & (HWN - 1));
#pragma unroll
        for (int c = 0; c < CC; c++) {
            float v = __ldg(cv + c);
            float zv = zp[(size_t)c * HWN];
            op[(size_t)c * HWN] = v;
            float df = v - zv;
            err = fmaf(df, df, err);
        }
    }
#pragma unroll
    for (int o = 16; o > 0; o >>= 1)
        err += __shfl_down_sync(0xFFFFFFFFu, err, o);
    if (l == 0) werr[w] = err;
    __syncthreads();
    if (tid == 0)
        g_partials[blockIdx.x] = werr[0] + werr[1] + werr[2] + werr[3];
}

// ---------------------------------------------------------------------------
// Kernel 2: deterministic loss = 1.25 * mean((z_q - z)^2)
// ---------------------------------------------------------------------------
__global__ void loss_kernel(float* __restrict__ loss_out) {
    __shared__ double s[512];
    s[threadIdx.x] = (double)g_partials[threadIdx.x] +
                     (double)g_partials[threadIdx.x + 512];
    __syncthreads();
#pragma unroll
    for (int st = 256; st > 0; st >>= 1) {
        if (threadIdx.x < st) s[threadIdx.x] += s[threadIdx.x + st];
        __syncthreads();
    }
    if (threadIdx.x == 0)
        loss_out[0] = (float)(1.25 * s[0] / (double)ZELEMS);
}

// ---------------------------------------------------------------------------
extern "C" void kernel_launch(void* const* d_in, const int* in_sizes, int n_in,
                              void* d_out, int out_size) {
    const float* z  = (const float*)d_in[0];
    const float* cb = (const float*)d_in[1];
    float* out = (float*)d_out;

    cudaFuncSetAttribute(vq_kernel, cudaFuncAttributeMaxDynamicSharedMemorySize,
                         SMEM_TOTAL);

    prep_kernel<<<4, 256>>>(cb);
    vq_kernel<<<NBLOCKS, THREADS, SMEM_TOTAL>>>(z, cb, out);
    if (out_size > ZELEMS)
        loss_kernel<<<1, 512>>>(out + ZELEMS);
}

// round 5
// speedup vs baseline: 1.5628x; 1.0819x over previous
#include <cuda_runtime.h>
#include <cuda_bf16.h>
#include <cstdint>

// Problem constants (z: [32,64,64,64] f32, codebook: [1024,64] f32)
#define BB      32
#define CC      64
#define HWN     4096
#define NQ      (BB * HWN)        // 131072 queries
#define KCODES  1024
#define MTILE   128               // queries per CTA
#define NCHUNK  128               // codes staged per smem chunk
#define THREADS 128
#define NBLOCKS (NQ / MTILE)      // 1024
#define ZELEMS  (BB * CC * HWN)
#define EPS     4e-3f
#define PADW    136               // bf16 row stride: 272B = 17*16B -> LDSM conflict-free

// dynamic smem layout (bytes) — AB region reused: A tile -> B chunks -> cand
#define OFF_AB   0                            // 128 x 136 bf16 = 34816
#define OFF_SCN  34816                        // 128 floats
#define OFF_WERR 35328                        // 4 floats
#define SMEM_TOTAL 35456

__device__ float g_cnorm[KCODES];
__device__ float g_partials[NBLOCKS];
// prepped codebook: bf16 hi/lo of (-2c), rows padded to PADW
__device__ __align__(16) __nv_bfloat16 g_cbimg[KCODES * PADW];

// ---------------------------------------------------------------------------
__device__ __forceinline__ uint32_t smem_to_u32(const void* p) {
    uint32_t a;
    asm("{ .reg .u64 t; cvta.to.shared.u64 t, %1; cvt.u32.u64 %0, t; }"
        : "=r"(a) : "l"(p));
    return a;
}

#define LDSM_X4(r, addr) \
    asm volatile("ldmatrix.sync.aligned.m8n8.x4.shared.b16 {%0,%1,%2,%3}, [%4];" \
        : "=r"((r)[0]), "=r"((r)[1]), "=r"((r)[2]), "=r"((r)[3]) : "r"(addr))

#define MMA16816(d, a, b) \
    asm volatile("mma.sync.aligned.m16n8k16.row.col.f32.bf16.bf16.f32 " \
        "{%0,%1,%2,%3}, {%4,%5,%6,%7}, {%8,%9}, {%0,%1,%2,%3};" \
        : "+f"((d)[0]), "+f"((d)[1]), "+f"((d)[2]), "+f"((d)[3]) \
        : "r"((a)[0]), "r"((a)[1]), "r"((a)[2]), "r"((a)[3]), \
          "r"((b)[0]), "r"((b)[1]))

__device__ __forceinline__ void top4_insert(float s, int idx, float* ts, int* ti) {
    if (s < ts[3]) {
        if (s < ts[0]) {
            ts[3]=ts[2]; ti[3]=ti[2]; ts[2]=ts[1]; ti[2]=ti[1];
            ts[1]=ts[0]; ti[1]=ti[0]; ts[0]=s; ti[0]=idx;
        } else if (s < ts[1]) {
            ts[3]=ts[2]; ti[3]=ti[2]; ts[2]=ts[1]; ti[2]=ti[1]; ts[1]=s; ti[1]=idx;
        } else if (s < ts[2]) {
            ts[3]=ts[2]; ti[3]=ti[2]; ts[2]=s; ti[2]=idx;
        } else {
            ts[3]=s; ti[3]=idx;
        }
    }
}

// ---------------------------------------------------------------------------
// Kernel 0: prep — cn = ||c||^2, bf16 hi/lo split of (-2c), padded rows
// ---------------------------------------------------------------------------
__global__ void prep_kernel(const float* __restrict__ cb) {
    int k = blockIdx.x * blockDim.x + threadIdx.x;
    if (k >= KCODES) return;
    const float2* r = reinterpret_cast<const float2*>(cb + (size_t)k * CC);
    __nv_bfloat16* row = g_cbimg + (size_t)k * PADW;
    float cn = 0.f;
#pragma unroll
    for (int c = 0; c < CC / 2; c++) {
        float2 v = __ldg(r + c);
        cn = fmaf(v.x, v.x, cn);
        cn = fmaf(v.y, v.y, cn);
        float s0 = -2.f * v.x, s1 = -2.f * v.y;
        __nv_bfloat16 h0 = __float2bfloat16_rn(s0);
        __nv_bfloat16 h1 = __float2bfloat16_rn(s1);
        __nv_bfloat162 hp; hp.x = h0; hp.y = h1;
        __nv_bfloat162 lp;
        lp.x = __float2bfloat16_rn(s0 - __bfloat162float(h0));
        lp.y = __float2bfloat16_rn(s1 - __bfloat162float(h1));
        *reinterpret_cast<__nv_bfloat162*>(row + 2 * c) = hp;
        *reinterpret_cast<__nv_bfloat162*>(row + CC + 2 * c) = lp;
    }
    g_cnorm[k] = cn;
}

// exact fp64 squared distance (refinement path)
__device__ double dist2_f64(const float* __restrict__ zp,
                            const float* __restrict__ cb, int idx) {
    const float* cp = cb + (size_t)idx * CC;
    double d = 0.0;
#pragma unroll
    for (int c = 0; c < CC; c++) {
        double df = (double)zp[(size_t)c * HWN] - (double)cp[c];
        d = fma(df, df, d);
    }
    return d;
}

// ---------------------------------------------------------------------------
// Kernel 1: HMMA VQ — D = cn - 2 z.c via mma.sync bf16x3, exact argmin
// ---------------------------------------------------------------------------
extern __shared__ unsigned char dynsmem[];

__global__ __launch_bounds__(THREADS, 3)
void vq_kernel(const float* __restrict__ z,
               const float* __restrict__ cb,
               float* __restrict__ out) {
    const int tid = threadIdx.x;
    const int w = tid >> 5;
    const int l = tid & 31;
    const uint32_t sb = smem_to_u32(dynsmem);

    __nv_bfloat16* A = reinterpret_cast<__nv_bfloat16*>(dynsmem + OFF_AB);
    float* scn  = reinterpret_cast<float*>(dynsmem + OFF_SCN);
    float* werr = reinterpret_cast<float*>(dynsmem + OFF_WERR);
    float2* cand = reinterpret_cast<float2*>(dynsmem + OFF_AB);  // reused post-loop

    const int q = blockIdx.x * MTILE + tid;
    const int b = q >> 12;
    const float* zp = z + (size_t)b * CC * HWN + (q & (HWN - 1));

    // --- A tile: z query -> bf16 hi/lo, row-major padded ---
#pragma unroll
    for (int c = 0; c < CC; c++) {
        float v = zp[(size_t)c * HWN];
        __nv_bfloat16 h = __float2bfloat16_rn(v);
        A[tid * PADW + c] = h;
        A[tid * PADW + CC + c] = __float2bfloat16_rn(v - __bfloat162float(h));
    }
    __syncthreads();

    // --- hoist A fragments to registers: 8 ka-slices x (a0[4], a1[4]) ---
    const int rowA = w * 32 + (l & 15);
    const int colA = ((l >> 4) & 1) * 8;
    uint32_t afr[64];
#pragma unroll
    for (int fi = 0; fi < 8; fi++) {
        LDSM_X4(afr + fi * 8,
                sb + OFF_AB + (uint32_t)((rowA)      * PADW + colA + fi * 16) * 2);
        LDSM_X4(afr + fi * 8 + 4,
                sb + OFF_AB + (uint32_t)((rowA + 16) * PADW + colA + fi * 16) * 2);
    }

    // per-thread top-4 over 4 query-slots (16 disjoint code-subsets)
    float ts[16];
    int   ti[16];
#pragma unroll
    for (int i = 0; i < 16; i++) { ts[i] = 3.4e38f; ti[i] = 0x7fffffff; }

    const int rowB = ((l >> 4) & 1) * 8 + (l & 7);
    const int colB = ((l >> 3) & 1) * 8;

    // stacked-K split schedule: zh*bh (4), zl*bh (4), zh*bl (4)
    // A frag index per step, B k-offset per step
    const int FA[12] = {0,1,2,3, 4,5,6,7, 0,1,2,3};
    const int KB[12] = {0,16,32,48, 0,16,32,48, 64,80,96,112};

    for (int ch = 0; ch < KCODES / NCHUNK; ch++) {
        __syncthreads();  // prev chunk fully consumed (AB reusable)
        // stage code chunk into AB region
        {
            const int4* src = reinterpret_cast<const int4*>(g_cbimg + (size_t)ch * NCHUNK * PADW);
            int4* dst = reinterpret_cast<int4*>(dynsmem + OFF_AB);
#pragma unroll 4
            for (int i = tid; i < NCHUNK * PADW * 2 / 16; i += THREADS) dst[i] = src[i];
            scn[tid] = g_cnorm[ch * NCHUNK + tid];
        }
        __syncthreads();

#pragma unroll 1
        for (int nsub = 0; nsub < 4; nsub++) {
            // accum init: d[(mt*4+nt)*4+e] = cn[n(e)]
            float d[32];
#pragma unroll
            for (int nt = 0; nt < 4; nt++) {
                float cn0 = scn[nsub * 32 + nt * 8 + 2 * (l & 3)];
                float cn1 = scn[nsub * 32 + nt * 8 + 2 * (l & 3) + 1];
#pragma unroll
                for (int mt = 0; mt < 2; mt++) {
                    d[(mt * 4 + nt) * 4 + 0] = cn0;
                    d[(mt * 4 + nt) * 4 + 1] = cn1;
                    d[(mt * 4 + nt) * 4 + 2] = cn0;
                    d[(mt * 4 + nt) * 4 + 3] = cn1;
                }
            }

#pragma unroll
            for (int step = 0; step < 12; step++) {
                const uint32_t* a0 = afr + FA[step] * 8;
                const uint32_t* a1 = a0 + 4;
                const int kb = KB[step];
                uint32_t bf[8];
                LDSM_X4(bf,     sb + OFF_AB + (uint32_t)((nsub * 32 +      rowB) * PADW + colB + kb) * 2);
                LDSM_X4(bf + 4, sb + OFF_AB + (uint32_t)((nsub * 32 + 16 + rowB) * PADW + colB + kb) * 2);
#pragma unroll
                for (int nt = 0; nt < 4; nt++) {
                    MMA16816(d + (0 * 4 + nt) * 4, a0, bf + nt * 2);
                    MMA16816(d + (1 * 4 + nt) * 4, a1, bf + nt * 2);
                }
            }

            // top-4 update: slot = mt*2 + (e>>1)
#pragma unroll
            for (int mt = 0; mt < 2; mt++)
#pragma unroll
                for (int nt = 0; nt < 4; nt++)
#pragma unroll
                    for (int e = 0; e < 4; e++) {
                        float s = d[(mt * 4 + nt) * 4 + e];
                        int idx = ch * NCHUNK + nsub * 32 + nt * 8 + 2 * (l & 3) + (e & 1);
                        int slot = mt * 2 + (e >> 1);
                        top4_insert(s, idx, ts + slot * 4, ti + slot * 4);
                    }
        }
    }

    // --- merge candidates via smem (stride 17 float2; reuses AB region) ---
    __syncthreads();
#pragma unroll
    for (int s = 0; s < 4; s++) {
        int mt = s >> 1, half = s & 1;
        int ql = w * 32 + mt * 16 + half * 8 + (l >> 2);
#pragma unroll
        for (int e = 0; e < 4; e++)
            cand[ql * 17 + (l & 3) * 4 + e] =
                make_float2(ts[s * 4 + e], __int_as_float(ti[s * 4 + e]));
    }
    __syncthreads();

    // --- per-query (thread = query): window + fp64 refinement ---
    float cs[16]; int ci[16];
#pragma unroll
    for (int j = 0; j < 16; j++) {
        float2 v = cand[tid * 17 + j];
        cs[j] = v.x; ci[j] = __float_as_int(v.y);
    }
    float smin = cs[0];
#pragma unroll
    for (int j = 1; j < 16; j++) smin = fminf(smin, cs[j]);

    int nwin = 0, lone = 0;
#pragma unroll
    for (int j = 0; j < 16; j++)
        if (cs[j] < smin + EPS) { nwin++; lone = j; }

    int bidx;
    if (nwin == 1) {
        bidx = ci[lone];
    } else {
        double bd = 1e300;
        int bi = 0x7fffffff;
#pragma unroll
        for (int j = 0; j < 16; j++) {
            if (cs[j] < smin + EPS) {
                double dd = dist2_f64(zp, cb, ci[j]);
                if (dd < bd || (dd == bd && ci[j] < bi)) { bd = dd; bi = ci[j]; }
            }
        }
        bidx = bi;
    }

    // --- write z_q + squared-error partial (coalesced: threads = consecutive n) ---
    float err = 0.f;
    {
        const float* cv = cb + (size_t)bidx * CC;
        float* op = out + (size_t)b * CC * HWN + (q & (HWN - 1));
#pragma unroll
        for (int c = 0; c < CC; c++) {
            float v = __ldg(cv + c);
            float zv = zp[(size_t)c * HWN];
            op[(size_t)c * HWN] = v;
            float df = v - zv;
            err = fmaf(df, df, err);
        }
    }
#pragma unroll
    for (int o = 16; o > 0; o >>= 1)
        err += __shfl_down_sync(0xFFFFFFFFu, err, o);
    if (l == 0) werr[w] = err;
    __syncthreads();
    if (tid == 0)
        g_partials[blockIdx.x] = werr[0] + werr[1] + werr[2] + werr[3];
}

// ---------------------------------------------------------------------------
// Kernel 2: deterministic loss = 1.25 * mean((z_q - z)^2)
// ---------------------------------------------------------------------------
__global__ void loss_kernel(float* __restrict__ loss_out) {
    __shared__ double s[512];
    s[threadIdx.x] = (double)g_partials[threadIdx.x] +
                     (double)g_partials[threadIdx.x + 512];
    __syncthreads();
#pragma unroll
    for (int st = 256; st > 0; st >>= 1) {
        if (threadIdx.x < st) s[threadIdx.x] += s[threadIdx.x + st];
        __syncthreads();
    }
    if (threadIdx.x == 0)
        loss_out[0] = (float)(1.25 * s[0] / (double)ZELEMS);
}

// ---------------------------------------------------------------------------
extern "C" void kernel_launch(void* const* d_in, const int* in_sizes, int n_in,
                              void* d_out, int out_size) {
    const float* z  = (const float*)d_in[0];
    const float* cb = (const float*)d_in[1];
    float* out = (float*)d_out;

    cudaFuncSetAttribute(vq_kernel, cudaFuncAttributeMaxDynamicSharedMemorySize,
                         SMEM_TOTAL);

    prep_kernel<<<8, 128>>>(cb);
    vq_kernel<<<NBLOCKS, THREADS, SMEM_TOTAL>>>(z, cb, out);
    if (out_size > ZELEMS)
        loss_kernel<<<1, 512>>>(out + ZELEMS);
}

// round 6
// speedup vs baseline: 1.6833x; 1.0771x over previous
#include <cuda_runtime.h>
#include <cuda_bf16.h>
#include <cstdint>

// Problem constants (z: [32,64,64,64] f32, codebook: [1024,64] f32)
#define BB      32
#define CC      64
#define HWN     4096
#define NQ      (BB * HWN)        // 131072 queries
#define KCODES  1024
#define MTILE   128               // queries per CTA
#define NCHUNK  128               // codes staged per smem chunk
#define THREADS 128
#define NBLOCKS (NQ / MTILE)      // 1024
#define ZELEMS  (BB * CC * HWN)
#define EPS     4e-3f
#define PADW    136               // B row stride (bf16): 272B = 17*16B, conflict-free
#define PADA    72                // A row stride (bf16): 144B = 9*16B, conflict-free

// dynamic smem layout (bytes)
// OFF_B region cycles: A-hi tile (transient) -> B chunks -> candidate buffer
#define OFF_ALO  0                             // 128 x 72 bf16 = 18432 (persistent z-lo)
#define OFF_B    18432                         // 128 x 136 bf16 = 34816
#define OFF_SCN  (OFF_B + 34816)               // 128 floats
#define OFF_WERR (OFF_SCN + 512)               // 4 floats
#define SMEM_TOTAL (OFF_WERR + 64)             // 53824

__device__ float g_cnorm[KCODES];
__device__ float g_partials[NBLOCKS];
// prepped codebook: bf16 hi/lo of (-2c), rows padded to PADW
__device__ __align__(16) __nv_bfloat16 g_cbimg[KCODES * PADW];

// ---------------------------------------------------------------------------
__device__ __forceinline__ uint32_t smem_to_u32(const void* p) {
    uint32_t a;
    asm("{ .reg .u64 t; cvta.to.shared.u64 t, %1; cvt.u32.u64 %0, t; }"
        : "=r"(a) : "l"(p));
    return a;
}

#define LDSM_X4(r, addr) \
    asm volatile("ldmatrix.sync.aligned.m8n8.x4.shared.b16 {%0,%1,%2,%3}, [%4];" \
        : "=r"((r)[0]), "=r"((r)[1]), "=r"((r)[2]), "=r"((r)[3]) : "r"(addr))

#define MMA16816(d, a, b) \
    asm volatile("mma.sync.aligned.m16n8k16.row.col.f32.bf16.bf16.f32 " \
        "{%0,%1,%2,%3}, {%4,%5,%6,%7}, {%8,%9}, {%0,%1,%2,%3};" \
        : "+f"((d)[0]), "+f"((d)[1]), "+f"((d)[2]), "+f"((d)[3]) \
        : "r"((a)[0]), "r"((a)[1]), "r"((a)[2]), "r"((a)[3]), \
          "r"((b)[0]), "r"((b)[1]))

__device__ __forceinline__ void top4_insert(float s, int idx, float* ts, int* ti) {
    if (s < ts[3]) {
        if (s < ts[0]) {
            ts[3]=ts[2]; ti[3]=ti[2]; ts[2]=ts[1]; ti[2]=ti[1];
            ts[1]=ts[0]; ti[1]=ti[0]; ts[0]=s; ti[0]=idx;
        } else if (s < ts[1]) {
            ts[3]=ts[2]; ti[3]=ti[2]; ts[2]=ts[1]; ti[2]=ti[1]; ts[1]=s; ti[1]=idx;
        } else if (s < ts[2]) {
            ts[3]=ts[2]; ti[3]=ti[2]; ts[2]=s; ti[2]=idx;
        } else {
            ts[3]=s; ti[3]=idx;
        }
    }
}

// ---------------------------------------------------------------------------
// Kernel 0: prep — cn = ||c||^2, bf16 hi/lo split of (-2c), padded rows
// ---------------------------------------------------------------------------
__global__ void prep_kernel(const float* __restrict__ cb) {
    int k = blockIdx.x * blockDim.x + threadIdx.x;
    if (k >= KCODES) return;
    const float2* r = reinterpret_cast<const float2*>(cb + (size_t)k * CC);
    __nv_bfloat16* row = g_cbimg + (size_t)k * PADW;
    float cn = 0.f;
#pragma unroll
    for (int c = 0; c < CC / 2; c++) {
        float2 v = __ldg(r + c);
        cn = fmaf(v.x, v.x, cn);
        cn = fmaf(v.y, v.y, cn);
        float s0 = -2.f * v.x, s1 = -2.f * v.y;
        __nv_bfloat16 h0 = __float2bfloat16_rn(s0);
        __nv_bfloat16 h1 = __float2bfloat16_rn(s1);
        __nv_bfloat162 hp; hp.x = h0; hp.y = h1;
        __nv_bfloat162 lp;
        lp.x = __float2bfloat16_rn(s0 - __bfloat162float(h0));
        lp.y = __float2bfloat16_rn(s1 - __bfloat162float(h1));
        *reinterpret_cast<__nv_bfloat162*>(row + 2 * c) = hp;
        *reinterpret_cast<__nv_bfloat162*>(row + CC + 2 * c) = lp;
    }
    g_cnorm[k] = cn;
}

// exact fp64 squared distance (refinement path)
__device__ double dist2_f64(const float* __restrict__ zp,
                            const float* __restrict__ cb, int idx) {
    const float* cp = cb + (size_t)idx * CC;
    double d = 0.0;
#pragma unroll
    for (int c = 0; c < CC; c++) {
        double df = (double)zp[(size_t)c * HWN] - (double)cp[c];
        d = fma(df, df, d);
    }
    return d;
}

// ---------------------------------------------------------------------------
// Kernel 1: HMMA VQ — D = cn - 2 z.c via mma.sync bf16x3, exact argmin
// ---------------------------------------------------------------------------
extern __shared__ unsigned char dynsmem[];

__global__ __launch_bounds__(THREADS, 3)
void vq_kernel(const float* __restrict__ z,
               const float* __restrict__ cb,
               float* __restrict__ out) {
    const int tid = threadIdx.x;
    const int w = tid >> 5;
    const int l = tid & 31;
    const uint32_t sb = smem_to_u32(dynsmem);

    __nv_bfloat16* Alo = reinterpret_cast<__nv_bfloat16*>(dynsmem + OFF_ALO);
    __nv_bfloat16* Ahi = reinterpret_cast<__nv_bfloat16*>(dynsmem + OFF_B); // transient
    float* scn  = reinterpret_cast<float*>(dynsmem + OFF_SCN);
    float* werr = reinterpret_cast<float*>(dynsmem + OFF_WERR);
    float2* cand = reinterpret_cast<float2*>(dynsmem + OFF_B);  // reused post-loop

    const int q = blockIdx.x * MTILE + tid;
    const int b = q >> 12;
    const float* zp = z + (size_t)b * CC * HWN + (q & (HWN - 1));

    // --- A tile: z query -> bf16 hi (transient) / lo (persistent) ---
#pragma unroll
    for (int c = 0; c < CC; c++) {
        float v = zp[(size_t)c * HWN];
        __nv_bfloat16 h = __float2bfloat16_rn(v);
        Ahi[tid * PADA + c] = h;
        Alo[tid * PADA + c] = __float2bfloat16_rn(v - __bfloat162float(h));
    }
    __syncthreads();

    // --- hoist zh fragments only: 4 k-slices x (a0[4], a1[4]) = 32 regs ---
    const int rowA = w * 32 + (l & 15);
    const int colA = ((l >> 4) & 1) * 8;
    uint32_t afr[32];
#pragma unroll
    for (int fi = 0; fi < 4; fi++) {
        LDSM_X4(afr + fi * 8,
                sb + OFF_B + (uint32_t)((rowA)      * PADA + colA + fi * 16) * 2);
        LDSM_X4(afr + fi * 8 + 4,
                sb + OFF_B + (uint32_t)((rowA + 16) * PADA + colA + fi * 16) * 2);
    }

    // per-thread top-4 over 4 query-slots (16 disjoint code-subsets)
    float ts[16];
    int   ti[16];
#pragma unroll
    for (int i = 0; i < 16; i++) { ts[i] = 3.4e38f; ti[i] = 0x7fffffff; }

    const int rowB = ((l >> 4) & 1) * 8 + (l & 7);
    const int colB = ((l >> 3) & 1) * 8;

#pragma unroll 1
    for (int ch = 0; ch < KCODES / NCHUNK; ch++) {
        __syncthreads();  // prev chunk fully consumed (B region reusable)
        // stage code chunk into B region
        {
            const int4* src = reinterpret_cast<const int4*>(g_cbimg + (size_t)ch * NCHUNK * PADW);
            int4* dst = reinterpret_cast<int4*>(dynsmem + OFF_B);
#pragma unroll 4
            for (int i = tid; i < NCHUNK * PADW * 2 / 16; i += THREADS) dst[i] = src[i];
            scn[tid] = g_cnorm[ch * NCHUNK + tid];
        }
        __syncthreads();

#pragma unroll 1
        for (int nsub = 0; nsub < 4; nsub++) {
            // accum init: d[(mt*4+nt)*4+e] = cn[n(e)]
            float d[32];
#pragma unroll
            for (int nt = 0; nt < 4; nt++) {
                float cn0 = scn[nsub * 32 + nt * 8 + 2 * (l & 3)];
                float cn1 = scn[nsub * 32 + nt * 8 + 2 * (l & 3) + 1];
#pragma unroll
                for (int mt = 0; mt < 2; mt++) {
                    d[(mt * 4 + nt) * 4 + 0] = cn0;
                    d[(mt * 4 + nt) * 4 + 1] = cn1;
                    d[(mt * 4 + nt) * 4 + 2] = cn0;
                    d[(mt * 4 + nt) * 4 + 3] = cn1;
                }
            }

            const uint32_t bbase = sb + OFF_B +
                (uint32_t)((nsub * 32 + rowB) * PADW + colB) * 2;

            // pass 1: zh * bh (4 steps, hoisted A)
#pragma unroll
            for (int s = 0; s < 4; s++) {
                uint32_t bf[8];
                LDSM_X4(bf,     bbase + (uint32_t)(s * 16) * 2);
                LDSM_X4(bf + 4, bbase + (uint32_t)(16 * PADW + s * 16) * 2);
                const uint32_t* a0 = afr + s * 8;
#pragma unroll
                for (int nt = 0; nt < 4; nt++) {
                    MMA16816(d + (0 * 4 + nt) * 4, a0,     bf + nt * 2);
                    MMA16816(d + (1 * 4 + nt) * 4, a0 + 4, bf + nt * 2);
                }
            }
            // pass 2: zl * bh (4 steps, A-lo streamed from smem)
#pragma unroll
            for (int s = 0; s < 4; s++) {
                uint32_t al[8], bf[8];
                LDSM_X4(al,     sb + OFF_ALO + (uint32_t)((rowA)      * PADA + colA + s * 16) * 2);
                LDSM_X4(al + 4, sb + OFF_ALO + (uint32_t)((rowA + 16) * PADA + colA + s * 16) * 2);
                LDSM_X4(bf,     bbase + (uint32_t)(s * 16) * 2);
                LDSM_X4(bf + 4, bbase + (uint32_t)(16 * PADW + s * 16) * 2);
#pragma unroll
                for (int nt = 0; nt < 4; nt++) {
                    MMA16816(d + (0 * 4 + nt) * 4, al,     bf + nt * 2);
                    MMA16816(d + (1 * 4 + nt) * 4, al + 4, bf + nt * 2);
                }
            }
            // pass 3: zh * bl (4 steps, hoisted A, B lo half)
#pragma unroll
            for (int s = 0; s < 4; s++) {
                uint32_t bf[8];
                LDSM_X4(bf,     bbase + (uint32_t)(64 + s * 16) * 2);
                LDSM_X4(bf + 4, bbase + (uint32_t)(16 * PADW + 64 + s * 16) * 2);
                const uint32_t* a0 = afr + s * 8;
#pragma unroll
                for (int nt = 0; nt < 4; nt++) {
                    MMA16816(d + (0 * 4 + nt) * 4, a0,     bf + nt * 2);
                    MMA16816(d + (1 * 4 + nt) * 4, a0 + 4, bf + nt * 2);
                }
            }

            // top-4 update: slot = mt*2 + (e>>1)
#pragma unroll
            for (int mt = 0; mt < 2; mt++)
#pragma unroll
                for (int nt = 0; nt < 4; nt++)
#pragma unroll
                    for (int e = 0; e < 4; e++) {
                        float s = d[(mt * 4 + nt) * 4 + e];
                        int idx = ch * NCHUNK + nsub * 32 + nt * 8 + 2 * (l & 3) + (e & 1);
                        int slot = mt * 2 + (e >> 1);
                        top4_insert(s, idx, ts + slot * 4, ti + slot * 4);
                    }
        }
    }

    // --- merge candidates via smem (stride 17 float2; reuses B region) ---
    __syncthreads();
#pragma unroll
    for (int s = 0; s < 4; s++) {
        int mt = s >> 1, half = s & 1;
        int ql = w * 32 + mt * 16 + half * 8 + (l >> 2);
#pragma unroll
        for (int e = 0; e < 4; e++)
            cand[ql * 17 + (l & 3) * 4 + e] =
                make_float2(ts[s * 4 + e], __int_as_float(ti[s * 4 + e]));
    }
    __syncthreads();

    // --- per-query (thread = query): window + fp64 refinement ---
    float cs[16]; int ci[16];
#pragma unroll
    for (int j = 0; j < 16; j++) {
        float2 v = cand[tid * 17 + j];
        cs[j] = v.x; ci[j] = __float_as_int(v.y);
    }
    float smin = cs[0];
#pragma unroll
    for (int j = 1; j < 16; j++) smin = fminf(smin, cs[j]);

    int nwin = 0, lone = 0;
#pragma unroll
    for (int j = 0; j < 16; j++)
        if (cs[j] < smin + EPS) { nwin++; lone = j; }

    int bidx;
    if (nwin == 1) {
        bidx = ci[lone];
    } else {
        double bd = 1e300;
        int bi = 0x7fffffff;
#pragma unroll
        for (int j = 0; j < 16; j++) {
            if (cs[j] < smin + EPS) {
                double dd = dist2_f64(zp, cb, ci[j]);
                if (dd < bd || (dd == bd && ci[j] < bi)) { bd = dd; bi = ci[j]; }
            }
        }
        bidx = bi;
    }

    // --- write z_q + squared-error partial (coalesced: threads = consecutive n) ---
    float err = 0.f;
    {
        const float* cv = cb + (size_t)bidx * CC;
        float* op = out + (size_t)b * CC * HWN + (q & (HWN - 1));
#pragma unroll
        for (int c = 0; c < CC; c++) {
            float v = __ldg(cv + c);
            float zv = zp[(size_t)c * HWN];
            op[(size_t)c * HWN] = v;
            float df = v - zv;
            err = fmaf(df, df, err);
        }
    }
#pragma unroll
    for (int o = 16; o > 0; o >>= 1)
        err += __shfl_down_sync(0xFFFFFFFFu, err, o);
    if (l == 0) werr[w] = err;
    __syncthreads();
    if (tid == 0)
        g_partials[blockIdx.x] = werr[0] + werr[1] + werr[2] + werr[3];
}

// ---------------------------------------------------------------------------
// Kernel 2: deterministic loss = 1.25 * mean((z_q - z)^2)
// ---------------------------------------------------------------------------
__global__ void loss_kernel(float* __restrict__ loss_out) {
    __shared__ double s[512];
    s[threadIdx.x] = (double)g_partials[threadIdx.x] +
                     (double)g_partials[threadIdx.x + 512];
    __syncthreads();
#pragma unroll
    for (int st = 256; st > 0; st >>= 1) {
        if (threadIdx.x < st) s[threadIdx.x] += s[threadIdx.x + st];
        __syncthreads();
    }
    if (threadIdx.x == 0)
        loss_out[0] = (float)(1.25 * s[0] / (double)ZELEMS);
}

// ---------------------------------------------------------------------------
extern "C" void kernel_launch(void* const* d_in, const int* in_sizes, int n_in,
                              void* d_out, int out_size) {
    const float* z  = (const float*)d_in[0];
    const float* cb = (const float*)d_in[1];
    float* out = (float*)d_out;

    cudaFuncSetAttribute(vq_kernel, cudaFuncAttributeMaxDynamicSharedMemorySize,
                         SMEM_TOTAL);

    prep_kernel<<<8, 128>>>(cb);
    vq_kernel<<<NBLOCKS, THREADS, SMEM_TOTAL>>>(z, cb, out);
    if (out_size > ZELEMS)
        loss_kernel<<<1, 512>>>(out + ZELEMS);
}